// round 9
// baseline (speedup 1.0000x reference)
#include <cuda_runtime.h>
#include <cuda_bf16.h>
#include <cstdint>

#define NPROMPT 50
#define MPAD 64
#define D 768
#define KC 64
#define NCHUNK (D / KC)      // 12
#define NTILE 128            // pe rows per CTA
#define NVEC 201728
#define NBLK (NVEC / NTILE)  // 1576
#define EPSV 1e-6f
#define NTHREADS 512
#define NSTAGE 3

#define LDA 72
#define LDB 72
#define SA_STAGE_B (MPAD * LDA * 2)    // 9216 bytes
#define SB_STAGE_B (NTILE * LDB * 2)   // 18432 bytes

__device__ __align__(16) __nv_bfloat16 g_B[MPAD * D];
__device__ float g_ns[MPAD];
__device__ double g_acc;

// ---------------------------------------------------------------- prep ----
__global__ void prep_kernel(const float* __restrict__ src) {
    int p = blockIdx.x, tid = threadIdx.x;
    float local = 0.f;
    for (int k = tid; k < D; k += blockDim.x) {
        float v = (p < NPROMPT) ? src[p * D + k] + EPSV : 0.f;
        g_B[p * D + k] = __float2bfloat16(v);
        local += v * v;
    }
    __shared__ float sh[256];
    sh[tid] = local;
    __syncthreads();
    for (int s = 128; s > 0; s >>= 1) {
        if (tid < s) sh[tid] += sh[tid + s];
        __syncthreads();
    }
    if (tid == 0) {
        g_ns[p] = sh[0];
        if (p == 0) g_acc = 0.0;
    }
}

// ------------------------------------------------------------- helpers ----
__device__ __forceinline__ uint32_t pack_bf2(float lo, float hi) {
    __nv_bfloat162 t = __floats2bfloat162_rn(lo, hi);
    return *reinterpret_cast<uint32_t*>(&t);
}

__device__ __forceinline__ void ldsm4(uint32_t& r0, uint32_t& r1, uint32_t& r2,
                                      uint32_t& r3, uint32_t addr) {
    asm volatile("ldmatrix.sync.aligned.m8n8.x4.shared.b16 {%0,%1,%2,%3}, [%4];\n"
                 : "=r"(r0), "=r"(r1), "=r"(r2), "=r"(r3)
                 : "r"(addr));
}

__device__ __forceinline__ void mma16816(float* c, uint32_t a0, uint32_t a1,
                                         uint32_t a2, uint32_t a3, uint32_t b0,
                                         uint32_t b1) {
    asm volatile(
        "mma.sync.aligned.m16n8k16.row.col.f32.bf16.bf16.f32 "
        "{%0,%1,%2,%3}, {%4,%5,%6,%7}, {%8,%9}, {%0,%1,%2,%3};\n"
        : "+f"(c[0]), "+f"(c[1]), "+f"(c[2]), "+f"(c[3])
        : "r"(a0), "r"(a1), "r"(a2), "r"(a3), "r"(b0), "r"(b1));
}

__device__ __forceinline__ void cp_async16(uint32_t dst, const void* src) {
    asm volatile("cp.async.cg.shared.global [%0], [%1], 16;" ::"r"(dst),
                 "l"(src)
                 : "memory");
}
#define CP_COMMIT() asm volatile("cp.async.commit_group;" ::: "memory")
#define CP_WAIT0() asm volatile("cp.async.wait_group 0;" ::: "memory")

__device__ __forceinline__ void mbar_init(uint32_t addr, uint32_t cnt) {
    asm volatile("mbarrier.init.shared.b64 [%0], %1;" ::"r"(addr), "r"(cnt)
                 : "memory");
}
__device__ __forceinline__ void mbar_arrive(uint32_t addr) {
    asm volatile("mbarrier.arrive.shared.b64 _, [%0];" ::"r"(addr) : "memory");
}
__device__ __forceinline__ void mbar_wait(uint32_t addr, uint32_t parity) {
    asm volatile(
        "{\n\t.reg .pred P;\n\t"
        "WL_%=:\n\t"
        "mbarrier.try_wait.parity.acquire.cta.shared::cta.b64 P, [%0], %1, 0x989680;\n\t"
        "@P bra.uni WD_%=;\n\t"
        "bra.uni WL_%=;\n\t"
        "WD_%=:\n\t}" ::"r"(addr),
        "r"(parity)
        : "memory");
}

// ---------------------------------------------------------------- main ----
// smem layout (bytes):
//   [0, 96)                      : 6 mbarriers (full[3], empty[3]) + pad
//   [96, ...)                    : sNpe[128], sNs[64], sRed[16] floats
//   aligned 1024                 : A stages [3 x 9216]
//   then                         : B stages [3 x 18432]
#define OFF_MBAR 0
#define OFF_NORM 96
#define OFF_SA   1024
#define OFF_SB   (OFF_SA + NSTAGE * SA_STAGE_B)
#define SMEM_TOTAL (OFF_SB + NSTAGE * SB_STAGE_B)

__global__ void __launch_bounds__(NTHREADS, 2)
dist_kernel(const float* __restrict__ pe) {
    extern __shared__ char smem[];
    const uint32_t smem_u = (uint32_t)__cvta_generic_to_shared(smem);
    float* sNpe = (float*)(smem + OFF_NORM);
    float* sNs = sNpe + NTILE;
    float* sRed = sNs + MPAD;

    const int tid = threadIdx.x;
    const int warp = tid >> 5, lane = tid & 31;
    const uint32_t mb_full = smem_u + OFF_MBAR;        // full[s] at +s*8
    const uint32_t mb_empty = smem_u + OFF_MBAR + 24;  // empty[s] at +s*8

    if (tid == 0) {
#pragma unroll
        for (int s = 0; s < NSTAGE; ++s) {
            mbar_init(mb_full + s * 8, 8);   // 8 producer warps
            mbar_init(mb_empty + s * 8, 8);  // 8 consumer warps
        }
    }
    if (tid < MPAD) sNs[tid] = g_ns[tid];
    __syncthreads();

    float lsum = 0.f;

    if (warp < 8) {
        // ===================== CONSUMER (MMA) =====================
        const int m_base = (warp >> 1) * 16;  // 4 groups over M=64
        const int n_base = (warp & 1) * 64;   // 2 groups over N=128

        float acc[8][4];
#pragma unroll
        for (int j = 0; j < 8; ++j)
#pragma unroll
            for (int q = 0; q < 4; ++q) acc[j][q] = 0.f;

        const uint32_t a_off =
            (uint32_t)((m_base + (lane & 15)) * LDA + (lane >> 4) * 8) * 2;
        const uint32_t b_row =
            (uint32_t)(n_base + ((lane >> 4) & 1) * 8 + (lane & 7));
        const uint32_t b_k = ((lane >> 3) & 1) * 8;

        int s = 0, ph = 0;
        for (int it = 0; it < NCHUNK; ++it) {
            mbar_wait(mb_full + s * 8, ph);
            const uint32_t abase = smem_u + OFF_SA + s * SA_STAGE_B;
            const uint32_t bbase = smem_u + OFF_SB + s * SB_STAGE_B;
#pragma unroll
            for (int st = 0; st < 4; ++st) {
                uint32_t a0, a1, a2, a3;
                ldsm4(a0, a1, a2, a3, abase + a_off + st * 16 * 2);
#pragma unroll
                for (int jj = 0; jj < 4; ++jj) {
                    uint32_t b0, b1, b2, b3;
                    uint32_t baddr =
                        bbase + ((b_row + jj * 16) * LDB + st * 16 + b_k) * 2;
                    ldsm4(b0, b1, b2, b3, baddr);
                    mma16816(acc[2 * jj], a0, a1, a2, a3, b0, b1);
                    mma16816(acc[2 * jj + 1], a0, a1, a2, a3, b2, b3);
                }
            }
            __syncwarp();
            if (lane == 0) mbar_arrive(mb_empty + s * 8);
            if (++s == NSTAGE) { s = 0; ph ^= 1; }
        }

        // epilogue needs sNpe from producers
        __syncthreads();

        const int r = lane >> 2, c2 = (lane & 3) * 2;
#pragma unroll
        for (int j = 0; j < 8; ++j) {
            int n = n_base + j * 8 + c2;
            float np0 = sNpe[n], np1 = sNpe[n + 1];
            int m0 = m_base + r;
            if (m0 < NPROMPT) {
                float ns0 = sNs[m0];
                lsum += sqrtf(fmaxf(ns0 + np0 - 2.f * acc[j][0], 0.f));
                lsum += sqrtf(fmaxf(ns0 + np1 - 2.f * acc[j][1], 0.f));
            }
            int m1 = m0 + 8;
            if (m1 < NPROMPT) {
                float ns1 = sNs[m1];
                lsum += sqrtf(fmaxf(ns1 + np0 - 2.f * acc[j][2], 0.f));
                lsum += sqrtf(fmaxf(ns1 + np1 - 2.f * acc[j][3], 0.f));
            }
        }
    } else {
        // ===================== PRODUCER (load/convert) =====================
        const int ptid = tid - 256;  // 0..255
        // B: thread owns pe row r0, 32-float half c0
        const float* peBase = pe + (size_t)blockIdx.x * NTILE * D;
        const int r0 = ptid >> 1;
        const int c0 = (ptid & 1) * 32;
        const float* rowPtr = peBase + (size_t)r0 * D + c0;
        float nacc = 0.f;

        // A: thread copies 2 consecutive 16B slots (row ra, slots qa, qa+1)
        const int ra = ptid >> 2;
        const int qa = (ptid & 3) * 2;
        const uint32_t aDst = smem_u + OFF_SA + (uint32_t)(ra * LDA + qa * 8) * 2;
        const __nv_bfloat16* aSrc = g_B + ra * D + qa * 8;

        float4 v[8];
#pragma unroll
        for (int j = 0; j < 8; ++j)
            v[j] = *(const float4*)(rowPtr + j * 4);  // chunk 0

        int s = 0, ph = 1;
        for (int it = 0; it < NCHUNK; ++it) {
            mbar_wait(mb_empty + s * 8, ph);
            // A via cp.async
            {
                uint32_t d = aDst + (uint32_t)(s * SA_STAGE_B);
                const __nv_bfloat16* sp = aSrc + it * KC;
                cp_async16(d, sp);
                cp_async16(d + 16, sp + 8);
                CP_COMMIT();
            }
            // B: convert staged regs -> bf16 smem, accumulate |pe|^2
            {
                __nv_bfloat16* dst =
                    (__nv_bfloat16*)(smem + OFF_SB + s * SB_STAGE_B) +
                    r0 * LDB + c0;
#pragma unroll
                for (int j = 0; j < 8; ++j) {
                    nacc += v[j].x * v[j].x + v[j].y * v[j].y +
                            v[j].z * v[j].z + v[j].w * v[j].w;
                    uint2 u;
                    u.x = pack_bf2(v[j].x, v[j].y);
                    u.y = pack_bf2(v[j].z, v[j].w);
                    *(uint2*)(dst + j * 4) = u;
                }
            }
            // prefetch next chunk's B into regs
            if (it + 1 < NCHUNK) {
                const float* p = rowPtr + (it + 1) * KC;
#pragma unroll
                for (int j = 0; j < 8; ++j) v[j] = *(const float4*)(p + j * 4);
            }
            CP_WAIT0();
            __syncwarp();
            if (lane == 0) mbar_arrive(mb_full + s * 8);
            if (++s == NSTAGE) { s = 0; ph ^= 1; }
        }

        // |pe|^2 per row: combine the two half-row partials
        nacc += __shfl_xor_sync(0xffffffffu, nacc, 1);
        if ((ptid & 1) == 0) sNpe[r0] = nacc;

        __syncthreads();  // pairs with consumer epilogue barrier
    }

    // ---- block reduction of lsum (consumers carry values; producers 0)
#pragma unroll
    for (int o = 16; o > 0; o >>= 1)
        lsum += __shfl_xor_sync(0xffffffffu, lsum, o);
    if (lane == 0) sRed[warp] = lsum;
    __syncthreads();
    if (warp == 0) {
        float sv = (lane < 16) ? sRed[lane] : 0.f;
#pragma unroll
        for (int o = 8; o > 0; o >>= 1)
            sv += __shfl_xor_sync(0xffffffffu, sv, o);
        if (lane == 0) atomicAdd(&g_acc, (double)sv);
    }
}

// -------------------------------------------------------------- finish ----
__global__ void finish_kernel(float* out) {
    out[0] = (float)(g_acc * (1.0 / ((double)NPROMPT * 197.0 * 1024.0)));
}

// -------------------------------------------------------------- launch ----
extern "C" void kernel_launch(void* const* d_in, const int* in_sizes, int n_in,
                              void* d_out, int out_size) {
    const float* src = (const float*)d_in[0];  // source_prompt [50,768]
    const float* pe = (const float*)d_in[1];   // patch_embeds [1024,197,768]
    float* out = (float*)d_out;

    cudaFuncSetAttribute(dist_kernel, cudaFuncAttributeMaxDynamicSharedMemorySize,
                         SMEM_TOTAL);

    prep_kernel<<<MPAD, 256>>>(src);
    dist_kernel<<<NBLK, NTHREADS, SMEM_TOTAL>>>(pe);
    finish_kernel<<<1, 1>>>(out);
}

// round 10
// speedup vs baseline: 1.2376x; 1.2376x over previous
#include <cuda_runtime.h>
#include <cuda_bf16.h>
#include <cstdint>

#define NPROMPT 50
#define MPAD 64              // padded prompt count (GEMM M)
#define D 768
#define KC 64                // k per chunk
#define NCHUNK (D / KC)      // 12
#define NTILE 128            // pe rows per CTA (GEMM N)
#define NVEC 201728          // 1024 * 197
#define NBLK (NVEC / NTILE)  // 1576 exactly
#define EPSV 1e-6f
#define NTHREADS 512

#define LDA 72               // A-chunk smem row stride (halves)
#define LDB 72               // B-chunk smem row stride (halves)

__device__ __align__(16) __nv_bfloat16 g_B[MPAD * D];
__device__ float g_ns[MPAD];
__device__ double g_acc;

// ---------------------------------------------------------------- prep ----
__global__ void prep_kernel(const float* __restrict__ src) {
    int p = blockIdx.x, tid = threadIdx.x;
    float local = 0.f;
    for (int k = tid; k < D; k += blockDim.x) {
        float v = (p < NPROMPT) ? src[p * D + k] + EPSV : 0.f;
        g_B[p * D + k] = __float2bfloat16(v);
        local += v * v;
    }
    __shared__ float sh[256];
    sh[tid] = local;
    __syncthreads();
    for (int s = 128; s > 0; s >>= 1) {
        if (tid < s) sh[tid] += sh[tid + s];
        __syncthreads();
    }
    if (tid == 0) {
        g_ns[p] = sh[0];
        if (p == 0) g_acc = 0.0;
    }
}

// ------------------------------------------------------------- helpers ----
__device__ __forceinline__ uint32_t pack_bf2(float lo, float hi) {
    __nv_bfloat162 t = __floats2bfloat162_rn(lo, hi);
    return *reinterpret_cast<uint32_t*>(&t);
}

__device__ __forceinline__ void ldsm4(uint32_t& r0, uint32_t& r1, uint32_t& r2,
                                      uint32_t& r3, uint32_t addr) {
    asm volatile("ldmatrix.sync.aligned.m8n8.x4.shared.b16 {%0,%1,%2,%3}, [%4];\n"
                 : "=r"(r0), "=r"(r1), "=r"(r2), "=r"(r3)
                 : "r"(addr));
}

__device__ __forceinline__ void mma16816(float* c, uint32_t a0, uint32_t a1,
                                         uint32_t a2, uint32_t a3, uint32_t b0,
                                         uint32_t b1) {
    asm volatile(
        "mma.sync.aligned.m16n8k16.row.col.f32.bf16.bf16.f32 "
        "{%0,%1,%2,%3}, {%4,%5,%6,%7}, {%8,%9}, {%0,%1,%2,%3};\n"
        : "+f"(c[0]), "+f"(c[1]), "+f"(c[2]), "+f"(c[3])
        : "r"(a0), "r"(a1), "r"(a2), "r"(a3), "r"(b0), "r"(b1));
}

__device__ __forceinline__ void cp_async16(uint32_t dst, const void* src) {
    asm volatile("cp.async.cg.shared.global [%0], [%1], 16;" ::"r"(dst),
                 "l"(src)
                 : "memory");
}
#define CP_COMMIT() asm volatile("cp.async.commit_group;" ::: "memory")
#define CP_WAIT0() asm volatile("cp.async.wait_group 0;" ::: "memory")

// ---------------------------------------------------------------- main ----
constexpr int SA_HALVES = 2 * MPAD * LDA;
constexpr int SB_HALVES = 2 * NTILE * LDB;
constexpr int SMEM_BYTES = (SA_HALVES + SB_HALVES) * 2 + (NTILE + MPAD + 16) * 4;

__global__ void __launch_bounds__(NTHREADS, 2)
dist_kernel(const float* __restrict__ pe) {
    extern __shared__ char smem_raw[];
    __nv_bfloat16* sA = (__nv_bfloat16*)smem_raw;
    __nv_bfloat16* sB = sA + SA_HALVES;
    float* sNpe = (float*)(sB + SB_HALVES);
    float* sNs = sNpe + NTILE;
    float* sRed = sNs + MPAD;

    const int tid = threadIdx.x;
    const int warp = tid >> 5, lane = tid & 31;
    const int m_base = (warp >> 2) * 16;  // 4 m-groups over M=64
    const int n_base = (warp & 3) * 32;   // 4 n-groups over N=128

    if (tid < MPAD) sNs[tid] = g_ns[tid];

    // B: 4 threads per pe row; thread owns 16-float quarter c0 of row r0
    const float* peBase = pe + (size_t)blockIdx.x * NTILE * D;
    const int r0 = tid >> 2;
    const int c0 = (tid & 3) * 16;
    const float* rowPtr = peBase + (size_t)r0 * D + c0;
    float nacc = 0.f;

    // A (cp.async): 8 threads per prompt row; thread copies 1 x 16B slot
    const int ra = tid >> 3;
    const int qa = tid & 7;
    const uint32_t sA_u = (uint32_t)__cvta_generic_to_shared(sA);
    const uint32_t sB_u = (uint32_t)__cvta_generic_to_shared(sB);
    const uint32_t aDst = sA_u + (uint32_t)(ra * LDA + qa * 8) * 2;
    const __nv_bfloat16* aSrc = g_B + ra * D + qa * 8;

    float4 vA[4], vB[4];

#define CPA_A(ck, buf)                                                        \
    {                                                                         \
        cp_async16(aDst + (uint32_t)((buf)*MPAD * LDA * 2),                   \
                   aSrc + (ck)*KC);                                           \
        CP_COMMIT();                                                          \
    }
#define LDG_B(ck, vv)                                                         \
    {                                                                         \
        const float* p = rowPtr + (ck)*KC;                                    \
        _Pragma("unroll") for (int j = 0; j < 4; ++j)                         \
            vv[j] = *(const float4*)(p + j * 4);                              \
    }
#define STS_B(buf, vv)                                                        \
    {                                                                         \
        __nv_bfloat16* dst = sB + (buf)*NTILE * LDB + r0 * LDB + c0;          \
        _Pragma("unroll") for (int j = 0; j < 4; ++j) {                       \
            nacc += vv[j].x * vv[j].x + vv[j].y * vv[j].y +                   \
                    vv[j].z * vv[j].z + vv[j].w * vv[j].w;                    \
            uint2 u;                                                          \
            u.x = pack_bf2(vv[j].x, vv[j].y);                                 \
            u.y = pack_bf2(vv[j].z, vv[j].w);                                 \
            *(uint2*)(dst + j * 4) = u;                                       \
        }                                                                     \
    }

    // accumulators: warp tile M16 x N32 -> 4 n8 tiles
    float acc[4][4];
#pragma unroll
    for (int j = 0; j < 4; ++j)
#pragma unroll
        for (int q = 0; q < 4; ++q) acc[j][q] = 0.f;

    const uint32_t a_off =
        (uint32_t)((m_base + (lane & 15)) * LDA + (lane >> 4) * 8) * 2;
    const uint32_t b_row = (uint32_t)(n_base + ((lane >> 4) & 1) * 8 + (lane & 7));
    const uint32_t b_k = ((lane >> 3) & 1) * 8;

#define STEP(s, abase, bbase)                                                 \
    {                                                                         \
        uint32_t a0, a1, a2, a3;                                              \
        ldsm4(a0, a1, a2, a3, (abase) + a_off + (s)*16 * 2);                  \
        _Pragma("unroll") for (int jj = 0; jj < 2; ++jj) {                    \
            uint32_t b0, b1, b2, b3;                                          \
            uint32_t baddr =                                                  \
                (bbase) + ((b_row + jj * 16) * LDB + (s)*16 + b_k) * 2;       \
            ldsm4(b0, b1, b2, b3, baddr);                                     \
            mma16816(acc[2 * jj], a0, a1, a2, a3, b0, b1);                    \
            mma16816(acc[2 * jj + 1], a0, a1, a2, a3, b2, b3);                \
        }                                                                     \
    }
#define STEPS4(buf)                                                           \
    {                                                                         \
        const uint32_t abase_ = sA_u + (uint32_t)((buf)*MPAD * LDA * 2);      \
        const uint32_t bbase_ = sB_u + (uint32_t)((buf)*NTILE * LDB * 2);     \
        STEP(0, abase_, bbase_);                                              \
        STEP(1, abase_, bbase_);                                              \
        STEP(2, abase_, bbase_);                                              \
        STEP(3, abase_, bbase_);                                              \
    }

    // ---- prologue: chunk0 -> buf0 (exposed once), chunk1 staged in vA
    LDG_B(0, vA);
    STS_B(0, vA);
    LDG_B(1, vA);          // vA now holds chunk1
    CPA_A(0, 0);
    CP_WAIT0();
    __syncthreads();

    // ---- main loop, unrolled x2: vA/vB ping-pong, LDG 2 chunks ahead
#pragma unroll 1
    for (int e = 0; e < NCHUNK; e += 2) {
        // even iter: read buf0; vA holds chunk e+1
        if (e + 2 < NCHUNK) LDG_B(e + 2, vB);
        STEPS4(0);
        if (e + 1 < NCHUNK) {
            STS_B(1, vA);
            CPA_A(e + 1, 1);
            CP_WAIT0();
        }
        __syncthreads();

        // odd iter: read buf1; vB holds chunk e+2
        if (e + 1 < NCHUNK) {
            if (e + 3 < NCHUNK) LDG_B(e + 3, vA);
            STEPS4(1);
            if (e + 2 < NCHUNK) {
                STS_B(0, vB);
                CPA_A(e + 2, 0);
                CP_WAIT0();
            }
            __syncthreads();
        }
    }

    // ---- |pe|^2 per row: combine the four quarter-row partials
    nacc += __shfl_xor_sync(0xffffffffu, nacc, 1);
    nacc += __shfl_xor_sync(0xffffffffu, nacc, 2);
    if ((tid & 3) == 0) sNpe[r0] = nacc;
    __syncthreads();

    // ---- epilogue: d = sqrt(|s'|^2 + |pe|^2 - 2 dot), mask prompts >= 50
    float lsum = 0.f;
    const int r = lane >> 2, c2 = (lane & 3) * 2;
#pragma unroll
    for (int j = 0; j < 4; ++j) {
        int n = n_base + j * 8 + c2;
        float np0 = sNpe[n], np1 = sNpe[n + 1];
        int m0 = m_base + r;
        if (m0 < NPROMPT) {
            float ns0 = sNs[m0];
            lsum += sqrtf(fmaxf(ns0 + np0 - 2.f * acc[j][0], 0.f));
            lsum += sqrtf(fmaxf(ns0 + np1 - 2.f * acc[j][1], 0.f));
        }
        int m1 = m0 + 8;
        if (m1 < NPROMPT) {
            float ns1 = sNs[m1];
            lsum += sqrtf(fmaxf(ns1 + np0 - 2.f * acc[j][2], 0.f));
            lsum += sqrtf(fmaxf(ns1 + np1 - 2.f * acc[j][3], 0.f));
        }
    }
#pragma unroll
    for (int o = 16; o > 0; o >>= 1)
        lsum += __shfl_xor_sync(0xffffffffu, lsum, o);
    if (lane == 0) sRed[warp] = lsum;
    __syncthreads();
    if (warp == 0) {
        float sv = (lane < 16) ? sRed[lane] : 0.f;
#pragma unroll
        for (int o = 8; o > 0; o >>= 1)
            sv += __shfl_xor_sync(0xffffffffu, sv, o);
        if (lane == 0) atomicAdd(&g_acc, (double)sv);
    }
}

// -------------------------------------------------------------- finish ----
__global__ void finish_kernel(float* out) {
    out[0] = (float)(g_acc * (1.0 / ((double)NPROMPT * 197.0 * 1024.0)));
}

// -------------------------------------------------------------- launch ----
extern "C" void kernel_launch(void* const* d_in, const int* in_sizes, int n_in,
                              void* d_out, int out_size) {
    const float* src = (const float*)d_in[0];  // source_prompt [50,768]
    const float* pe = (const float*)d_in[1];   // patch_embeds [1024,197,768]
    float* out = (float*)d_out;

    cudaFuncSetAttribute(dist_kernel, cudaFuncAttributeMaxDynamicSharedMemorySize,
                         SMEM_BYTES);

    prep_kernel<<<MPAD, 256>>>(src);
    dist_kernel<<<NBLK, NTHREADS, SMEM_BYTES>>>(pe);
    finish_kernel<<<1, 1>>>(out);
}

// round 11
// speedup vs baseline: 1.4277x; 1.1537x over previous
#include <cuda_runtime.h>
#include <cuda_bf16.h>
#include <cstdint>

#define NPROMPT 50
#define MPAD 64              // padded prompt count (GEMM M)
#define D 768
#define KC 64                // k per chunk
#define NCHUNK (D / KC)      // 12
#define NTILE 128            // pe rows per CTA (GEMM N)
#define NVEC 201728          // 1024 * 197
#define NBLK (NVEC / NTILE)  // 1576 exactly
#define EPSV 1e-6f
#define NTHREADS 512

// 128B rows, XOR swizzle on 16B slots: phys byte = row*128 + ((slot^(row&7))<<4)
#define SW16(row, slot) ((uint32_t)((row)*128 + ((((slot) ^ ((row)&7))) << 4)))

__device__ __align__(16) __nv_bfloat16 g_B[MPAD * D];
__device__ float g_ns[MPAD];
__device__ double g_acc;

// ---------------------------------------------------------------- prep ----
__global__ void prep_kernel(const float* __restrict__ src) {
    int p = blockIdx.x, tid = threadIdx.x;
    float local = 0.f;
    for (int k = tid; k < D; k += blockDim.x) {
        float v = (p < NPROMPT) ? src[p * D + k] + EPSV : 0.f;
        g_B[p * D + k] = __float2bfloat16(v);
        local += v * v;
    }
    __shared__ float sh[256];
    sh[tid] = local;
    __syncthreads();
    for (int s = 128; s > 0; s >>= 1) {
        if (tid < s) sh[tid] += sh[tid + s];
        __syncthreads();
    }
    if (tid == 0) {
        g_ns[p] = sh[0];
        if (p == 0) g_acc = 0.0;
    }
}

// ------------------------------------------------------------- helpers ----
__device__ __forceinline__ uint32_t pack_bf2(float lo, float hi) {
    __nv_bfloat162 t = __floats2bfloat162_rn(lo, hi);
    return *reinterpret_cast<uint32_t*>(&t);
}

__device__ __forceinline__ void ldsm4(uint32_t& r0, uint32_t& r1, uint32_t& r2,
                                      uint32_t& r3, uint32_t addr) {
    asm volatile("ldmatrix.sync.aligned.m8n8.x4.shared.b16 {%0,%1,%2,%3}, [%4];\n"
                 : "=r"(r0), "=r"(r1), "=r"(r2), "=r"(r3)
                 : "r"(addr));
}

__device__ __forceinline__ void mma16816(float* c, uint32_t a0, uint32_t a1,
                                         uint32_t a2, uint32_t a3, uint32_t b0,
                                         uint32_t b1) {
    asm volatile(
        "mma.sync.aligned.m16n8k16.row.col.f32.bf16.bf16.f32 "
        "{%0,%1,%2,%3}, {%4,%5,%6,%7}, {%8,%9}, {%0,%1,%2,%3};\n"
        : "+f"(c[0]), "+f"(c[1]), "+f"(c[2]), "+f"(c[3])
        : "r"(a0), "r"(a1), "r"(a2), "r"(a3), "r"(b0), "r"(b1));
}

__device__ __forceinline__ void cp_async16(uint32_t dst, const void* src) {
    asm volatile("cp.async.cg.shared.global [%0], [%1], 16;" ::"r"(dst),
                 "l"(src)
                 : "memory");
}
#define CP_COMMIT() asm volatile("cp.async.commit_group;" ::: "memory")
#define CP_WAIT0() asm volatile("cp.async.wait_group 0;" ::: "memory")

// ---------------------------------------------------------------- main ----
// smem: A db [2 x 64 x 128B] = 16KB, B db [2 x 128 x 128B] = 32KB,
//       norms ~0.9KB -> ~49KB, 2 CTAs/SM
constexpr int SA_BYTES = 2 * MPAD * 128;
constexpr int SB_BYTES = 2 * NTILE * 128;
constexpr int SMEM_BYTES = SA_BYTES + SB_BYTES + (NTILE + MPAD + 16) * 4;

__global__ void __launch_bounds__(NTHREADS, 2)
dist_kernel(const float* __restrict__ pe) {
    extern __shared__ char smem_raw[];
    char* sA = smem_raw;
    char* sB = sA + SA_BYTES;
    float* sNpe = (float*)(sB + SB_BYTES);
    float* sNs = sNpe + NTILE;
    float* sRed = sNs + MPAD;

    const int tid = threadIdx.x;
    const int warp = tid >> 5, lane = tid & 31;
    const int m_base = (warp >> 2) * 16;  // 4 m-groups over M=64
    const int n_base = (warp & 3) * 32;   // 4 n-groups over N=128

    if (tid < MPAD) sNs[tid] = g_ns[tid];

    // B loader: 4 threads/row; thread owns 16-float quarter of row r0
    const float* peBase = pe + (size_t)blockIdx.x * NTILE * D;
    const int r0 = tid >> 2;          // 0..127
    const int q4 = tid & 3;           // quarter index
    const float* rowPtr = peBase + (size_t)r0 * D + q4 * 16;
    float nacc = 0.f;

    // A loader (cp.async): 8 threads/row; thread copies 16B slot qa of row ra
    const int ra = tid >> 3;
    const int qa = tid & 7;
    const uint32_t sA_u = (uint32_t)__cvta_generic_to_shared(sA);
    const uint32_t sB_u = (uint32_t)__cvta_generic_to_shared(sB);
    const uint32_t aDst = sA_u + SW16(ra, qa);
    const __nv_bfloat16* aSrc = g_B + ra * D + qa * 8;

    // B store phys addresses (two swizzled 16B slots per thread)
    const int bs0 = q4 * 2;
    const uint32_t bDst0 = sB_u + SW16(r0, bs0);
    const uint32_t bDst1 = sB_u + SW16(r0, bs0 + 1);

    float4 v[4];

#define CPA_A(ck, buf)                                                        \
    {                                                                         \
        cp_async16(aDst + (uint32_t)((buf)*MPAD * 128), aSrc + (ck)*KC);      \
        CP_COMMIT();                                                          \
    }
#define LDG_B(ck)                                                             \
    {                                                                         \
        const float* p = rowPtr + (ck)*KC;                                    \
        _Pragma("unroll") for (int j = 0; j < 4; ++j)                         \
            v[j] = *(const float4*)(p + j * 4);                               \
    }
#define STS_B(buf)                                                            \
    {                                                                         \
        uint4 u0, u1;                                                         \
        u0.x = pack_bf2(v[0].x, v[0].y); u0.y = pack_bf2(v[0].z, v[0].w);     \
        u0.z = pack_bf2(v[1].x, v[1].y); u0.w = pack_bf2(v[1].z, v[1].w);     \
        u1.x = pack_bf2(v[2].x, v[2].y); u1.y = pack_bf2(v[2].z, v[2].w);     \
        u1.z = pack_bf2(v[3].x, v[3].y); u1.w = pack_bf2(v[3].z, v[3].w);     \
        _Pragma("unroll") for (int j = 0; j < 4; ++j)                         \
            nacc += v[j].x * v[j].x + v[j].y * v[j].y + v[j].z * v[j].z +     \
                    v[j].w * v[j].w;                                          \
        uint32_t off = (uint32_t)((buf)*NTILE * 128);                         \
        asm volatile("st.shared.v4.b32 [%0], {%1,%2,%3,%4};" ::               \
                         "r"(bDst0 + off), "r"(u0.x), "r"(u0.y), "r"(u0.z),   \
                         "r"(u0.w));                                          \
        asm volatile("st.shared.v4.b32 [%0], {%1,%2,%3,%4};" ::               \
                         "r"(bDst1 + off), "r"(u1.x), "r"(u1.y), "r"(u1.z),   \
                         "r"(u1.w));                                          \
    }

    // accumulators: warp tile M16 x N32 -> 4 n8 tiles
    float acc[4][4];
#pragma unroll
    for (int j = 0; j < 4; ++j)
#pragma unroll
        for (int q = 0; q < 4; ++q) acc[j][q] = 0.f;

    // ldsm lane geometry
    const int a_row = m_base + (lane & 15);
    const uint32_t a_rowbase = sA_u + (uint32_t)(a_row * 128);
    const int a_e = a_row & 7;
    const int a_s0 = lane >> 4;  // 0 or 1

    const int b_row = n_base + ((lane >> 4) & 1) * 8 + (lane & 7);
    const uint32_t b_rowbase = sB_u + (uint32_t)(b_row * 128);
    const int b_e = b_row & 7;
    const int b_s0 = (lane >> 3) & 1;

#define STEP(s, aoff, boff)                                                   \
    {                                                                         \
        uint32_t a0, a1, a2, a3;                                              \
        ldsm4(a0, a1, a2, a3,                                                 \
              a_rowbase + (aoff) + (uint32_t)(((a_s0 + 2 * (s)) ^ a_e) << 4));\
        uint32_t bsl = (uint32_t)(((b_s0 + 2 * (s)) ^ b_e) << 4);             \
        _Pragma("unroll") for (int jj = 0; jj < 2; ++jj) {                    \
            uint32_t b0, b1, b2, b3;                                          \
            ldsm4(b0, b1, b2, b3,                                             \
                  b_rowbase + (boff) + (uint32_t)(jj * 16 * 128) + bsl);      \
            mma16816(acc[2 * jj], a0, a1, a2, a3, b0, b1);                    \
            mma16816(acc[2 * jj + 1], a0, a1, a2, a3, b2, b3);                \
        }                                                                     \
    }
#define STEPS4(buf)                                                           \
    {                                                                         \
        const uint32_t aoff_ = (uint32_t)((buf)*MPAD * 128);                  \
        const uint32_t boff_ = (uint32_t)((buf)*NTILE * 128);                 \
        STEP(0, aoff_, boff_);                                                \
        STEP(1, aoff_, boff_);                                                \
        STEP(2, aoff_, boff_);                                                \
        STEP(3, aoff_, boff_);                                                \
    }

    // ---- prologue: chunk0 -> buf0; v <- chunk1
    LDG_B(0);
    STS_B(0);
    CPA_A(0, 0);
    LDG_B(1);
    CP_WAIT0();
    __syncthreads();

    // ---- skewed pipeline: per iter — CPA(it+1) | STEPS(it) | STS(it+1) | LDG(it+2)
#pragma unroll 1
    for (int it = 0; it < NCHUNK; ++it) {
        const int cur = it & 1, nxt = (it + 1) & 1;
        if (it + 1 < NCHUNK) CPA_A(it + 1, nxt);
        STEPS4(cur);
        if (it + 1 < NCHUNK) STS_B(nxt);
        if (it + 2 < NCHUNK) LDG_B(it + 2);
        if (it + 1 < NCHUNK) CP_WAIT0();
        __syncthreads();
    }

    // ---- |pe|^2 per row: combine the four quarter-row partials
    nacc += __shfl_xor_sync(0xffffffffu, nacc, 1);
    nacc += __shfl_xor_sync(0xffffffffu, nacc, 2);
    if ((tid & 3) == 0) sNpe[r0] = nacc;
    __syncthreads();

    // ---- epilogue: d = sqrt(|s'|^2 + |pe|^2 - 2 dot), mask prompts >= 50
    float lsum = 0.f;
    const int r = lane >> 2, c2 = (lane & 3) * 2;
#pragma unroll
    for (int j = 0; j < 4; ++j) {
        int n = n_base + j * 8 + c2;
        float np0 = sNpe[n], np1 = sNpe[n + 1];
        int m0 = m_base + r;
        if (m0 < NPROMPT) {
            float ns0 = sNs[m0];
            lsum += sqrtf(fmaxf(ns0 + np0 - 2.f * acc[j][0], 0.f));
            lsum += sqrtf(fmaxf(ns0 + np1 - 2.f * acc[j][1], 0.f));
        }
        int m1 = m0 + 8;
        if (m1 < NPROMPT) {
            float ns1 = sNs[m1];
            lsum += sqrtf(fmaxf(ns1 + np0 - 2.f * acc[j][2], 0.f));
            lsum += sqrtf(fmaxf(ns1 + np1 - 2.f * acc[j][3], 0.f));
        }
    }
#pragma unroll
    for (int o = 16; o > 0; o >>= 1)
        lsum += __shfl_xor_sync(0xffffffffu, lsum, o);
    if (lane == 0) sRed[warp] = lsum;
    __syncthreads();
    if (warp == 0) {
        float sv = (lane < 16) ? sRed[lane] : 0.f;
#pragma unroll
        for (int o = 8; o > 0; o >>= 1)
            sv += __shfl_xor_sync(0xffffffffu, sv, o);
        if (lane == 0) atomicAdd(&g_acc, (double)sv);
    }
}

// -------------------------------------------------------------- finish ----
__global__ void finish_kernel(float* out) {
    out[0] = (float)(g_acc * (1.0 / ((double)NPROMPT * 197.0 * 1024.0)));
}

// -------------------------------------------------------------- launch ----
extern "C" void kernel_launch(void* const* d_in, const int* in_sizes, int n_in,
                              void* d_out, int out_size) {
    const float* src = (const float*)d_in[0];  // source_prompt [50,768]
    const float* pe = (const float*)d_in[1];   // patch_embeds [1024,197,768]
    float* out = (float*)d_out;

    cudaFuncSetAttribute(dist_kernel, cudaFuncAttributeMaxDynamicSharedMemorySize,
                         SMEM_BYTES);

    prep_kernel<<<MPAD, 256>>>(src);
    dist_kernel<<<NBLK, NTHREADS, SMEM_BYTES>>>(pe);
    finish_kernel<<<1, 1>>>(out);
}

// round 12
// speedup vs baseline: 1.6363x; 1.1461x over previous
#include <cuda_runtime.h>
#include <cuda_bf16.h>
#include <cstdint>

#define NPROMPT 50
#define MPAD 64              // padded prompt count (GEMM M)
#define D 768
#define KC 64                // k per chunk
#define NCHUNK (D / KC)      // 12
#define NTILE 128            // pe rows per CTA (GEMM N)
#define NVEC 201728          // 1024 * 197
#define NBLK (NVEC / NTILE)  // 1576 exactly
#define EPSV 1e-6f
#define NTHREADS 512

#define LDA 72               // A-chunk smem row stride (halves)
#define LDB 72               // B-chunk smem row stride (halves)

__device__ __align__(16) __nv_bfloat16 g_B[MPAD * D];
__device__ float g_ns[MPAD];
__device__ double g_acc;

// ---------------------------------------------------------------- prep ----
__global__ void prep_kernel(const float* __restrict__ src) {
    int p = blockIdx.x, tid = threadIdx.x;
    float local = 0.f;
    for (int k = tid; k < D; k += blockDim.x) {
        float v = (p < NPROMPT) ? src[p * D + k] + EPSV : 0.f;
        g_B[p * D + k] = __float2bfloat16(v);
        local += v * v;
    }
    __shared__ float sh[256];
    sh[tid] = local;
    __syncthreads();
    for (int s = 128; s > 0; s >>= 1) {
        if (tid < s) sh[tid] += sh[tid + s];
        __syncthreads();
    }
    if (tid == 0) {
        g_ns[p] = sh[0];
        if (p == 0) g_acc = 0.0;
    }
}

// ------------------------------------------------------------- helpers ----
__device__ __forceinline__ uint32_t pack_bf2(float lo, float hi) {
    __nv_bfloat162 t = __floats2bfloat162_rn(lo, hi);
    return *reinterpret_cast<uint32_t*>(&t);
}

__device__ __forceinline__ void ldsm4(uint32_t& r0, uint32_t& r1, uint32_t& r2,
                                      uint32_t& r3, uint32_t addr) {
    asm volatile("ldmatrix.sync.aligned.m8n8.x4.shared.b16 {%0,%1,%2,%3}, [%4];\n"
                 : "=r"(r0), "=r"(r1), "=r"(r2), "=r"(r3)
                 : "r"(addr));
}

__device__ __forceinline__ void mma16816(float* c, uint32_t a0, uint32_t a1,
                                         uint32_t a2, uint32_t a3, uint32_t b0,
                                         uint32_t b1) {
    asm volatile(
        "mma.sync.aligned.m16n8k16.row.col.f32.bf16.bf16.f32 "
        "{%0,%1,%2,%3}, {%4,%5,%6,%7}, {%8,%9}, {%0,%1,%2,%3};\n"
        : "+f"(c[0]), "+f"(c[1]), "+f"(c[2]), "+f"(c[3])
        : "r"(a0), "r"(a1), "r"(a2), "r"(a3), "r"(b0), "r"(b1));
}

__device__ __forceinline__ void cp_async16(uint32_t dst, const void* src) {
    asm volatile("cp.async.cg.shared.global [%0], [%1], 16;" ::"r"(dst),
                 "l"(src)
                 : "memory");
}
#define CP_COMMIT() asm volatile("cp.async.commit_group;" ::: "memory")
#define CP_WAIT0() asm volatile("cp.async.wait_group 0;" ::: "memory")

// ---------------------------------------------------------------- main ----
constexpr int SA_HALVES = 2 * MPAD * LDA;
constexpr int SB_HALVES = 2 * NTILE * LDB;
constexpr int SMEM_BYTES = (SA_HALVES + SB_HALVES) * 2 + (NTILE + MPAD + 16) * 4;

__global__ void __launch_bounds__(NTHREADS, 2)
dist_kernel(const float* __restrict__ pe) {
    extern __shared__ char smem_raw[];
    __nv_bfloat16* sA = (__nv_bfloat16*)smem_raw;
    __nv_bfloat16* sB = sA + SA_HALVES;
    float* sNpe = (float*)(sB + SB_HALVES);
    float* sNs = sNpe + NTILE;
    float* sRed = sNs + MPAD;

    const int tid = threadIdx.x;
    const int warp = tid >> 5, lane = tid & 31;
    const int m_base = (warp >> 2) * 16;  // 4 m-groups over M=64
    const int n_base = (warp & 3) * 32;   // 4 n-groups over N=128

    if (tid < MPAD) sNs[tid] = g_ns[tid];

    // B loader: 4 threads per pe row. COALESCED mapping: thread's j-th load
    // is at q*16B + j*64B, so per-instruction lanes 0-3 cover 64B contiguous.
    const float* peBase = pe + (size_t)blockIdx.x * NTILE * D;
    const int r0 = tid >> 2;           // 0..127
    const int q4 = tid & 3;            // 16B sub-slot
    const float* rowPtr = peBase + (size_t)r0 * D + q4 * 4;  // +q*16B
    float nacc = 0.f;

    // A (cp.async): 8 threads per prompt row; thread copies 1 x 16B slot
    const int ra = tid >> 3;
    const int qa = tid & 7;
    const uint32_t sA_u = (uint32_t)__cvta_generic_to_shared(sA);
    const uint32_t sB_u = (uint32_t)__cvta_generic_to_shared(sB);
    const uint32_t aDst = sA_u + (uint32_t)(ra * LDA + qa * 8) * 2;
    const __nv_bfloat16* aSrc = g_B + ra * D + qa * 8;

    float4 v[4];

#define CPA_A(ck, buf)                                                        \
    {                                                                         \
        cp_async16(aDst + (uint32_t)((buf)*MPAD * LDA * 2),                   \
                   aSrc + (ck)*KC);                                           \
        CP_COMMIT();                                                          \
    }
#define LDG_B(ck)                                                             \
    {                                                                         \
        const float* p = rowPtr + (ck)*KC;                                    \
        _Pragma("unroll") for (int j = 0; j < 4; ++j)                         \
            v[j] = *(const float4*)(p + j * 16); /* +j*64B: coalesced */      \
    }
#define STS_B(buf)                                                            \
    {                                                                         \
        __nv_bfloat16* dst = sB + (buf)*NTILE * LDB + r0 * LDB + q4 * 4;      \
        _Pragma("unroll") for (int j = 0; j < 4; ++j) {                       \
            nacc += v[j].x * v[j].x + v[j].y * v[j].y + v[j].z * v[j].z +     \
                    v[j].w * v[j].w;                                          \
            uint2 u;                                                          \
            u.x = pack_bf2(v[j].x, v[j].y);                                   \
            u.y = pack_bf2(v[j].z, v[j].w);                                   \
            *(uint2*)(dst + j * 16) = u; /* halves: +j*16 = +j*32B */         \
        }                                                                     \
    }

    // accumulators: warp tile M16 x N32 -> 4 n8 tiles
    float acc[4][4];
#pragma unroll
    for (int j = 0; j < 4; ++j)
#pragma unroll
        for (int q = 0; q < 4; ++q) acc[j][q] = 0.f;

    const uint32_t a_off =
        (uint32_t)((m_base + (lane & 15)) * LDA + (lane >> 4) * 8) * 2;
    const uint32_t b_row = (uint32_t)(n_base + ((lane >> 4) & 1) * 8 + (lane & 7));
    const uint32_t b_k = ((lane >> 3) & 1) * 8;

#define STEP(s, abase, bbase)                                                 \
    {                                                                         \
        uint32_t a0, a1, a2, a3;                                              \
        ldsm4(a0, a1, a2, a3, (abase) + a_off + (s)*16 * 2);                  \
        _Pragma("unroll") for (int jj = 0; jj < 2; ++jj) {                    \
            uint32_t b0, b1, b2, b3;                                          \
            uint32_t baddr =                                                  \
                (bbase) + ((b_row + jj * 16) * LDB + (s)*16 + b_k) * 2;       \
            ldsm4(b0, b1, b2, b3, baddr);                                     \
            mma16816(acc[2 * jj], a0, a1, a2, a3, b0, b1);                    \
            mma16816(acc[2 * jj + 1], a0, a1, a2, a3, b2, b3);                \
        }                                                                     \
    }

    // prologue: chunk 0 -> buffer 0
    CPA_A(0, 0);
    LDG_B(0);
    STS_B(0);
    CP_WAIT0();
    __syncthreads();

#pragma unroll 1
    for (int it = 0; it < NCHUNK; ++it) {
        const uint32_t abase = sA_u + (uint32_t)((it & 1) * MPAD * LDA * 2);
        const uint32_t bbase = sB_u + (uint32_t)((it & 1) * NTILE * LDB * 2);
        const bool dl = (it + 1) < NCHUNK;
        const int nb = (it + 1) & 1;

        if (dl) { LDG_B(it + 1); CPA_A(it + 1, nb); }  // full-chunk prefetch
        STEP(0, abase, bbase);
        STEP(1, abase, bbase);
        STEP(2, abase, bbase);
        STEP(3, abase, bbase);
        if (dl) { STS_B(nb); CP_WAIT0(); }
        __syncthreads();
    }

    // ---- |pe|^2 per row: combine the four quarter-row partials
    nacc += __shfl_xor_sync(0xffffffffu, nacc, 1);
    nacc += __shfl_xor_sync(0xffffffffu, nacc, 2);
    if ((tid & 3) == 0) sNpe[r0] = nacc;
    __syncthreads();

    // ---- epilogue: d = sqrt(|s'|^2 + |pe|^2 - 2 dot), mask prompts >= 50
    float lsum = 0.f;
    const int r = lane >> 2, c2 = (lane & 3) * 2;
#pragma unroll
    for (int j = 0; j < 4; ++j) {
        int n = n_base + j * 8 + c2;
        float np0 = sNpe[n], np1 = sNpe[n + 1];
        int m0 = m_base + r;
        if (m0 < NPROMPT) {
            float ns0 = sNs[m0];
            lsum += sqrtf(fmaxf(ns0 + np0 - 2.f * acc[j][0], 0.f));
            lsum += sqrtf(fmaxf(ns0 + np1 - 2.f * acc[j][1], 0.f));
        }
        int m1 = m0 + 8;
        if (m1 < NPROMPT) {
            float ns1 = sNs[m1];
            lsum += sqrtf(fmaxf(ns1 + np0 - 2.f * acc[j][2], 0.f));
            lsum += sqrtf(fmaxf(ns1 + np1 - 2.f * acc[j][3], 0.f));
        }
    }
#pragma unroll
    for (int o = 16; o > 0; o >>= 1)
        lsum += __shfl_xor_sync(0xffffffffu, lsum, o);
    if (lane == 0) sRed[warp] = lsum;
    __syncthreads();
    if (warp == 0) {
        float sv = (lane < 16) ? sRed[lane] : 0.f;
#pragma unroll
        for (int o = 8; o > 0; o >>= 1)
            sv += __shfl_xor_sync(0xffffffffu, sv, o);
        if (lane == 0) atomicAdd(&g_acc, (double)sv);
    }
}

// -------------------------------------------------------------- finish ----
__global__ void finish_kernel(float* out) {
    out[0] = (float)(g_acc * (1.0 / ((double)NPROMPT * 197.0 * 1024.0)));
}

// -------------------------------------------------------------- launch ----
extern "C" void kernel_launch(void* const* d_in, const int* in_sizes, int n_in,
                              void* d_out, int out_size) {
    const float* src = (const float*)d_in[0];  // source_prompt [50,768]
    const float* pe = (const float*)d_in[1];   // patch_embeds [1024,197,768]
    float* out = (float*)d_out;

    cudaFuncSetAttribute(dist_kernel, cudaFuncAttributeMaxDynamicSharedMemorySize,
                         SMEM_BYTES);

    prep_kernel<<<MPAD, 256>>>(src);
    dist_kernel<<<NBLK, NTHREADS, SMEM_BYTES>>>(pe);
    finish_kernel<<<1, 1>>>(out);
}

// round 13
// speedup vs baseline: 1.6446x; 1.0050x over previous
#include <cuda_runtime.h>
#include <cuda_bf16.h>
#include <cstdint>

#define NPROMPT 50
#define MPAD 64              // padded prompt count (GEMM M)
#define D 768
#define KC 64                // k per chunk
#define NCHUNK (D / KC)      // 12
#define NTILE 128            // pe rows per CTA tile (GEMM N)
#define NVEC 201728          // 1024 * 197
#define NBLK (NVEC / NTILE)  // 1576 tiles
#define EPSV 1e-6f
#define NTHREADS 512
#define GRID 296             // 148 SMs x 2 CTAs (persistent)

#define LDA 72               // A-chunk smem row stride (halves)
#define LDB 72               // B-chunk smem row stride (halves)

__device__ __align__(16) __nv_bfloat16 g_B[MPAD * D];
__device__ float g_ns[MPAD];
__device__ double g_acc;
__device__ int g_tile;

// ---------------------------------------------------------------- prep ----
__global__ void prep_kernel(const float* __restrict__ src) {
    int p = blockIdx.x, tid = threadIdx.x;
    float local = 0.f;
    for (int k = tid; k < D; k += blockDim.x) {
        float v = (p < NPROMPT) ? src[p * D + k] + EPSV : 0.f;
        g_B[p * D + k] = __float2bfloat16(v);
        local += v * v;
    }
    __shared__ float sh[256];
    sh[tid] = local;
    __syncthreads();
    for (int s = 128; s > 0; s >>= 1) {
        if (tid < s) sh[tid] += sh[tid + s];
        __syncthreads();
    }
    if (tid == 0) {
        g_ns[p] = sh[0];
        if (p == 0) { g_acc = 0.0; g_tile = 0; }
    }
}

// ------------------------------------------------------------- helpers ----
__device__ __forceinline__ uint32_t pack_bf2(float lo, float hi) {
    __nv_bfloat162 t = __floats2bfloat162_rn(lo, hi);
    return *reinterpret_cast<uint32_t*>(&t);
}

__device__ __forceinline__ void ldsm4(uint32_t& r0, uint32_t& r1, uint32_t& r2,
                                      uint32_t& r3, uint32_t addr) {
    asm volatile("ldmatrix.sync.aligned.m8n8.x4.shared.b16 {%0,%1,%2,%3}, [%4];\n"
                 : "=r"(r0), "=r"(r1), "=r"(r2), "=r"(r3)
                 : "r"(addr));
}

__device__ __forceinline__ void mma16816(float* c, uint32_t a0, uint32_t a1,
                                         uint32_t a2, uint32_t a3, uint32_t b0,
                                         uint32_t b1) {
    asm volatile(
        "mma.sync.aligned.m16n8k16.row.col.f32.bf16.bf16.f32 "
        "{%0,%1,%2,%3}, {%4,%5,%6,%7}, {%8,%9}, {%0,%1,%2,%3};\n"
        : "+f"(c[0]), "+f"(c[1]), "+f"(c[2]), "+f"(c[3])
        : "r"(a0), "r"(a1), "r"(a2), "r"(a3), "r"(b0), "r"(b1));
}

__device__ __forceinline__ void cp_async16(uint32_t dst, const void* src) {
    asm volatile("cp.async.cg.shared.global [%0], [%1], 16;" ::"r"(dst),
                 "l"(src)
                 : "memory");
}
#define CP_COMMIT() asm volatile("cp.async.commit_group;" ::: "memory")
#define CP_WAIT0() asm volatile("cp.async.wait_group 0;" ::: "memory")

// ---------------------------------------------------------------- main ----
constexpr int SA_HALVES = 2 * MPAD * LDA;
constexpr int SB_HALVES = 2 * NTILE * LDB;
constexpr int SMEM_BYTES =
    (SA_HALVES + SB_HALVES) * 2 + (NTILE + MPAD + 16 + 4) * 4;

__global__ void __launch_bounds__(NTHREADS, 2)
dist_kernel(const float* __restrict__ pe) {
    extern __shared__ char smem_raw[];
    __nv_bfloat16* sA = (__nv_bfloat16*)smem_raw;
    __nv_bfloat16* sB = sA + SA_HALVES;
    float* sNpe = (float*)(sB + SB_HALVES);
    float* sNs = sNpe + NTILE;
    float* sRed = sNs + MPAD;
    int* sTile = (int*)(sRed + 16);

    const int tid = threadIdx.x;
    const int warp = tid >> 5, lane = tid & 31;
    const int m_base = (warp >> 2) * 16;  // 4 m-groups over M=64
    const int n_base = (warp & 3) * 32;   // 4 n-groups over N=128

    if (tid < MPAD) sNs[tid] = g_ns[tid];

    // B loader mapping (coalesced): thread's j-th load at q*16B + j*64B
    const int r0 = tid >> 2;           // 0..127
    const int q4 = tid & 3;            // 16B sub-slot
    const size_t rowOff = (size_t)r0 * D + q4 * 4;

    // A (cp.async): 8 threads per prompt row; thread copies 1 x 16B slot
    const int ra = tid >> 3;
    const int qa = tid & 7;
    const uint32_t sA_u = (uint32_t)__cvta_generic_to_shared(sA);
    const uint32_t sB_u = (uint32_t)__cvta_generic_to_shared(sB);
    const uint32_t aDst = sA_u + (uint32_t)(ra * LDA + qa * 8) * 2;
    const __nv_bfloat16* aSrc = g_B + ra * D + qa * 8;

    const uint32_t a_off =
        (uint32_t)((m_base + (lane & 15)) * LDA + (lane >> 4) * 8) * 2;
    const uint32_t b_row = (uint32_t)(n_base + ((lane >> 4) & 1) * 8 + (lane & 7));
    const uint32_t b_k = ((lane >> 3) & 1) * 8;
    const int er = lane >> 2, ec2 = (lane & 3) * 2;

    float4 v[4];
    float lsum = 0.f;

#define CPA_A(ck, buf)                                                        \
    {                                                                         \
        cp_async16(aDst + (uint32_t)((buf)*MPAD * LDA * 2),                   \
                   aSrc + (ck)*KC);                                           \
        CP_COMMIT();                                                          \
    }
#define LDG_B(ck)                                                             \
    {                                                                         \
        const float* p = rowPtr + (ck)*KC;                                    \
        _Pragma("unroll") for (int j = 0; j < 4; ++j)                         \
            v[j] = *(const float4*)(p + j * 16);                              \
    }
#define STS_B(buf)                                                            \
    {                                                                         \
        __nv_bfloat16* dst = sB + (buf)*NTILE * LDB + r0 * LDB + q4 * 4;      \
        _Pragma("unroll") for (int j = 0; j < 4; ++j) {                       \
            nacc += v[j].x * v[j].x + v[j].y * v[j].y + v[j].z * v[j].z +     \
                    v[j].w * v[j].w;                                          \
            uint2 u;                                                          \
            u.x = pack_bf2(v[j].x, v[j].y);                                   \
            u.y = pack_bf2(v[j].z, v[j].w);                                   \
            *(uint2*)(dst + j * 16) = u;                                      \
        }                                                                     \
    }
#define STEP(s, abase, bbase)                                                 \
    {                                                                         \
        uint32_t a0, a1, a2, a3;                                              \
        ldsm4(a0, a1, a2, a3, (abase) + a_off + (s)*16 * 2);                  \
        _Pragma("unroll") for (int jj = 0; jj < 2; ++jj) {                    \
            uint32_t b0, b1, b2, b3;                                          \
            uint32_t baddr =                                                  \
                (bbase) + ((b_row + jj * 16) * LDB + (s)*16 + b_k) * 2;       \
            ldsm4(b0, b1, b2, b3, baddr);                                     \
            mma16816(acc[2 * jj], a0, a1, a2, a3, b0, b1);                    \
            mma16816(acc[2 * jj + 1], a0, a1, a2, a3, b2, b3);                \
        }                                                                     \
    }

    // ================= persistent tile loop =================
    for (;;) {
        if (tid == 0) *sTile = atomicAdd(&g_tile, 1);
        __syncthreads();
        const int t = *sTile;
        if (t >= NBLK) break;

        const float* rowPtr = pe + (size_t)t * NTILE * D + rowOff;
        float nacc = 0.f;
        float acc[4][4];
#pragma unroll
        for (int j = 0; j < 4; ++j)
#pragma unroll
            for (int q = 0; q < 4; ++q) acc[j][q] = 0.f;

        // prologue: chunk 0 -> buffer 0
        CPA_A(0, 0);
        LDG_B(0);
        STS_B(0);
        CP_WAIT0();
        __syncthreads();

#pragma unroll 1
        for (int it = 0; it < NCHUNK; ++it) {
            const uint32_t abase = sA_u + (uint32_t)((it & 1) * MPAD * LDA * 2);
            const uint32_t bbase = sB_u + (uint32_t)((it & 1) * NTILE * LDB * 2);
            const bool dl = (it + 1) < NCHUNK;
            const int nb = (it + 1) & 1;

            if (dl) { LDG_B(it + 1); CPA_A(it + 1, nb); }
            STEP(0, abase, bbase);
            STEP(1, abase, bbase);
            STEP(2, abase, bbase);
            STEP(3, abase, bbase);
            if (dl) { STS_B(nb); CP_WAIT0(); }
            __syncthreads();
        }

        // |pe|^2 per row: combine the four quarter-row partials
        nacc += __shfl_xor_sync(0xffffffffu, nacc, 1);
        nacc += __shfl_xor_sync(0xffffffffu, nacc, 2);
        if ((tid & 3) == 0) sNpe[r0] = nacc;
        __syncthreads();

        // epilogue: d = sqrt(|s'|^2 + |pe|^2 - 2 dot), mask prompts >= 50
#pragma unroll
        for (int j = 0; j < 4; ++j) {
            int n = n_base + j * 8 + ec2;
            float np0 = sNpe[n], np1 = sNpe[n + 1];
            int m0 = m_base + er;
            if (m0 < NPROMPT) {
                float ns0 = sNs[m0];
                lsum += sqrtf(fmaxf(ns0 + np0 - 2.f * acc[j][0], 0.f));
                lsum += sqrtf(fmaxf(ns0 + np1 - 2.f * acc[j][1], 0.f));
            }
            int m1 = m0 + 8;
            if (m1 < NPROMPT) {
                float ns1 = sNs[m1];
                lsum += sqrtf(fmaxf(ns1 + np0 - 2.f * acc[j][2], 0.f));
                lsum += sqrtf(fmaxf(ns1 + np1 - 2.f * acc[j][3], 0.f));
            }
        }
        // next iteration's tile-fetch __syncthreads orders sNpe reuse
    }

    // ---- block reduction of lsum across all tiles this CTA processed
#pragma unroll
    for (int o = 16; o > 0; o >>= 1)
        lsum += __shfl_xor_sync(0xffffffffu, lsum, o);
    if (lane == 0) sRed[warp] = lsum;
    __syncthreads();
    if (warp == 0) {
        float sv = (lane < 16) ? sRed[lane] : 0.f;
#pragma unroll
        for (int o = 8; o > 0; o >>= 1)
            sv += __shfl_xor_sync(0xffffffffu, sv, o);
        if (lane == 0) atomicAdd(&g_acc, (double)sv);
    }
}

// -------------------------------------------------------------- finish ----
__global__ void finish_kernel(float* out) {
    out[0] = (float)(g_acc * (1.0 / ((double)NPROMPT * 197.0 * 1024.0)));
}

// -------------------------------------------------------------- launch ----
extern "C" void kernel_launch(void* const* d_in, const int* in_sizes, int n_in,
                              void* d_out, int out_size) {
    const float* src = (const float*)d_in[0];  // source_prompt [50,768]
    const float* pe = (const float*)d_in[1];   // patch_embeds [1024,197,768]
    float* out = (float*)d_out;

    cudaFuncSetAttribute(dist_kernel, cudaFuncAttributeMaxDynamicSharedMemorySize,
                         SMEM_BYTES);

    prep_kernel<<<MPAD, 256>>>(src);
    dist_kernel<<<GRID, NTHREADS, SMEM_BYTES>>>(pe);
    finish_kernel<<<1, 1>>>(out);
}